// round 1
// baseline (speedup 1.0000x reference)
#include <cuda_runtime.h>

// DTM (distance-to-measure) on a 64x64 integer grid.
// Per (b,c) slice: bound = 0.05 * sum(w). Per point p: walk grid points in
// order of increasing squared distance, accumulate weight until crossing
// bound, output sqrt((sum_{d<d*} d^2 w + d*^2 (bound - cum_before)) / bound).
// Equivalent to the reference top_k formulation (weights >= 0 => crossing is
// always within max_k; value is order-invariant within equal-d^2 groups).

#define GW 64
#define HW 4096
#define NSLICE 12
#define NOFF (127 * 127)       // 16129 offsets (dy,dx) in [-63,63]^2
#define ND2 (2 * 63 * 63 + 1)  // 7939 possible d^2 values
#define PREF 2048              // shared-memory prefix of the sorted table

__device__ int g_counts[ND2];
__device__ int g_cursor[ND2];
__device__ unsigned g_table[NOFF];  // packed: d2<<14 | (dy+63)<<7 | (dx+63)

// ---- table build: histogram -> scan -> scatter (bucket sort by d^2) ----

__global__ void k_zero() {
    int i = blockIdx.x * blockDim.x + threadIdx.x;
    if (i < ND2) g_counts[i] = 0;
}

__global__ void k_hist() {
    int i = blockIdx.x * blockDim.x + threadIdx.x;
    if (i >= NOFF) return;
    int dy = i / 127 - 63;
    int dx = i % 127 - 63;
    atomicAdd(&g_counts[dy * dy + dx * dx], 1);
}

__global__ void k_scan() {
    __shared__ int part[1024];
    int t = threadIdx.x;
    int base = t * 8;
    int loc[8];
    int s = 0;
#pragma unroll
    for (int k = 0; k < 8; k++) {
        int v = (base + k < ND2) ? g_counts[base + k] : 0;
        loc[k] = s;
        s += v;
    }
    part[t] = s;
    __syncthreads();
    for (int off = 1; off < 1024; off <<= 1) {
        int v = (t >= off) ? part[t - off] : 0;
        __syncthreads();
        part[t] += v;
        __syncthreads();
    }
    int pre = (t > 0) ? part[t - 1] : 0;
#pragma unroll
    for (int k = 0; k < 8; k++)
        if (base + k < ND2) g_cursor[base + k] = pre + loc[k];
}

__global__ void k_scatter() {
    int i = blockIdx.x * blockDim.x + threadIdx.x;
    if (i >= NOFF) return;
    int dy = i / 127 - 63;
    int dx = i % 127 - 63;
    int d2 = dy * dy + dx * dx;
    int pos = atomicAdd(&g_cursor[d2], 1);
    g_table[pos] =
        ((unsigned)d2 << 14) | ((unsigned)(dy + 63) << 7) | (unsigned)(dx + 63);
}

// ---- main kernel: one block = (slice, 128-point chunk) ----

__global__ void __launch_bounds__(128)
k_main(const float* __restrict__ x, float* __restrict__ out) {
    __shared__ float sw[HW];
    __shared__ __align__(16) unsigned soff[PREF];
    __shared__ float red[128];

    int slice = blockIdx.x >> 5;  // 32 chunks of 128 points per slice
    int chunk = blockIdx.x & 31;
    const float* src = x + slice * HW;
    int t = threadIdx.x;

    float lsum = 0.f;
    for (int i = t; i < HW; i += 128) {
        float v = src[i];
        sw[i] = v;
        lsum += v;
    }
    for (int i = t; i < PREF; i += 128) soff[i] = g_table[i];
    red[t] = lsum;
    __syncthreads();
#pragma unroll
    for (int s = 64; s > 0; s >>= 1) {
        if (t < s) red[t] += red[t + s];
        __syncthreads();
    }
    float bound = 0.05f * red[0];

    int p = (chunk << 7) + t;
    int row = p >> 6;
    int col = p & 63;

    float cum = 0.f, acc = 0.f, res = -1.f;
    int i = 0;

    // fast path over shared prefix, unrolled x4 with group-sum crossing test
    for (; i < PREF; i += 4) {
        uint4 ev = *(const uint4*)&soff[i];
        unsigned ee[4] = {ev.x, ev.y, ev.z, ev.w};
        float w[4], d2f[4];
#pragma unroll
        for (int k = 0; k < 4; k++) {
            unsigned e = ee[k];
            int rr = row + (int)((e >> 7) & 127u) - 63;
            int cc = col + (int)(e & 127u) - 63;
            bool v = ((unsigned)rr < 64u) & ((unsigned)cc < 64u);
            int idx = v ? ((rr << 6) + cc) : 0;
            float ww = sw[idx];
            w[k] = v ? ww : 0.f;
            d2f[k] = (float)(e >> 14);
        }
        float s = (w[0] + w[1]) + (w[2] + w[3]);
        if (cum + s >= bound) {
            // slow path: elementwise (weights >= 0 => group test is exact,
            // up to fp rounding; if no element crosses, keep scanning)
            bool crossed = false;
#pragma unroll
            for (int k = 0; k < 4; k++) {
                if (!crossed) {
                    float nc = cum + w[k];
                    if (nc >= bound) {
                        acc += d2f[k] * (bound - cum);
                        res = acc;
                        crossed = true;
                    } else {
                        cum = nc;
                        acc += d2f[k] * w[k];
                    }
                }
            }
            if (crossed) break;
        } else {
            cum += s;
            acc += d2f[0] * w[0];
            acc += d2f[1] * w[1];
            acc += d2f[2] * w[2];
            acc += d2f[3] * w[3];
        }
    }

    // rare fallback: continue from global table beyond the prefix
    if (res < 0.f) {
        for (; i < NOFF; ++i) {
            unsigned e = g_table[i];
            int rr = row + (int)((e >> 7) & 127u) - 63;
            int cc = col + (int)(e & 127u) - 63;
            bool v = ((unsigned)rr < 64u) & ((unsigned)cc < 64u);
            int idx = v ? ((rr << 6) + cc) : 0;
            float ww = sw[idx];
            ww = v ? ww : 0.f;
            float d2f = (float)(e >> 14);
            float nc = cum + ww;
            if (nc >= bound) {
                acc += d2f * (bound - cum);
                res = acc;
                break;
            }
            cum = nc;
            acc += d2f * ww;
        }
        if (res < 0.f) res = acc;  // rounding guard: never crossed
    }

    out[slice * HW + p] = sqrtf(res / bound);
}

extern "C" void kernel_launch(void* const* d_in, const int* in_sizes, int n_in,
                              void* d_out, int out_size) {
    const float* x = (const float*)d_in[0];
    float* out = (float*)d_out;

    k_zero<<<(ND2 + 255) / 256, 256>>>();
    k_hist<<<(NOFF + 255) / 256, 256>>>();
    k_scan<<<1, 1024>>>();
    k_scatter<<<(NOFF + 255) / 256, 256>>>();
    k_main<<<NSLICE * 32, 128>>>(x, out);
}